// round 14
// baseline (speedup 1.0000x reference)
#include <cuda_runtime.h>
#include <cuda_fp16.h>

#define TQ 64
#define TK 128
#define NB 32
#define ND 1024
#define GSTRIDE 72   // gemm smem row stride in halves

// Static scratch (no allocations allowed)
__device__ __align__(16) __half g_pq[TQ * NB * ND];
__device__ __align__(16) __half g_pk[TK * NB * ND];
__device__ __align__(16) __half g_vh[ND];
__device__ __align__(16) __half g_part_h[8 * NB * TQ * TK];// [z][b][tq][k] fp16
__device__ __align__(16) __half g_qh[TQ * NB * ND];
__device__ __align__(16) __half g_kh[TK * NB * ND];
__device__ __align__(16) __half g_wqh[ND * ND];
__device__ __align__(16) __half g_wkh[ND * ND];
__device__ int g_cnt[8];   // per-u-column completion counters (48 each)

// ---------------------------------------------------------------------------
// helpers
// ---------------------------------------------------------------------------
__device__ __forceinline__ __half2 htanh2(__half2 x) {
    unsigned xi = *reinterpret_cast<unsigned*>(&x);
    unsigned ri;
    asm("tanh.approx.f16x2 %0, %1;" : "=r"(ri) : "r"(xi));
    return *reinterpret_cast<__half2*>(&ri);
}

// Pade [7/6] tanh on FMA/ALU pipes (no MUFU). Clamp to +-4.
__device__ __forceinline__ __half2 ptanh2(__half2 x) {
    x = __hmin2(__hmax2(x, __float2half2_rn(-4.0f)), __float2half2_rn(4.0f));
    __half2 t = __hmul2(x, x);
    __half2 p = __hfma2(__float2half2_rn(5.92008e-5f), t,
                        __float2half2_rn(2.237786e-2f));
    p = __hfma2(p, t, __float2half2_rn(1.0256410f));
    p = __hfma2(p, t, __float2half2_rn(8.0f));
    p = __hmul2(p, x);                                   // numerator
    __half2 qn = __hfma2(__float2half2_rn(-1.657604e-3f), t,
                         __float2half2_rn(-0.18648246f));
    qn = __hfma2(qn, t, __float2half2_rn(-3.6923077f));
    qn = __hfma2(qn, t, __float2half2_rn(-8.0f));        // -denominator
    unsigned dpos = (*reinterpret_cast<unsigned*>(&qn)) ^ 0x80008000u;
    unsigned r0b = __vsub2(0x78007800u, dpos);           // ~1/den bit trick
    __half2 r = *reinterpret_cast<__half2*>(&r0b);
    const __half2 two = __float2half2_rn(2.0f);
    r = __hmul2(r, __hfma2(qn, r, two));                 // Newton 1
    r = __hmul2(r, __hfma2(qn, r, two));                 // Newton 2
    return __hmul2(p, r);
}

__device__ __forceinline__ void ldm_x4(unsigned& r0, unsigned& r1,
                                       unsigned& r2, unsigned& r3,
                                       const void* p) {
    unsigned addr = (unsigned)__cvta_generic_to_shared(p);
    asm volatile("ldmatrix.sync.aligned.m8n8.x4.shared.b16 {%0,%1,%2,%3}, [%4];"
                 : "=r"(r0), "=r"(r1), "=r"(r2), "=r"(r3) : "r"(addr));
}

__device__ __forceinline__ void ldm_x4_trans(unsigned& r0, unsigned& r1,
                                             unsigned& r2, unsigned& r3,
                                             const void* p) {
    unsigned addr = (unsigned)__cvta_generic_to_shared(p);
    asm volatile("ldmatrix.sync.aligned.m8n8.x4.trans.shared.b16 {%0,%1,%2,%3}, [%4];"
                 : "=r"(r0), "=r"(r1), "=r"(r2), "=r"(r3) : "r"(addr));
}

__device__ __forceinline__ void mma16816h(float* c, const unsigned* a,
                                          const unsigned* b) {
    asm volatile(
        "mma.sync.aligned.m16n8k16.row.col.f32.f16.f16.f32 "
        "{%0,%1,%2,%3}, {%4,%5,%6,%7}, {%8,%9}, {%0,%1,%2,%3};"
        : "+f"(c[0]), "+f"(c[1]), "+f"(c[2]), "+f"(c[3])
        : "r"(a[0]), "r"(a[1]), "r"(a[2]), "r"(a[3]), "r"(b[0]), "r"(b[1]));
}

__device__ __forceinline__ void cp_async16(void* smem_dst, const void* gsrc) {
    unsigned d = (unsigned)__cvta_generic_to_shared(smem_dst);
    asm volatile("cp.async.cg.shared.global [%0], [%1], 16;" :: "r"(d), "l"(gsrc));
}

// ---------------------------------------------------------------------------
// Kernel A: convert fp32 -> fp16, 8 floats/thread (2xLDG.128 -> 1xSTG.128).
// Segments in thread-units (2 float4 each): q 262144 | k 524288 | wq/wk 131072.
// Last block (4096) preps v and resets flags.
// ---------------------------------------------------------------------------
__global__ __launch_bounds__(256) void k_convert(const float* __restrict__ q,
                                                 const float* __restrict__ k,
                                                 const float* __restrict__ wq,
                                                 const float* __restrict__ wk,
                                                 const float* __restrict__ la,
                                                 const float* __restrict__ ns) {
    if (blockIdx.x == 4096) {
        __shared__ float red[256];
        int t = threadIdx.x;
        if (t < 8) g_cnt[t] = 0;
        float s = 0.f;
        for (int i = t; i < ND; i += 256) { float x = la[i]; s += x * x; }
        red[t] = s;
        __syncthreads();
        for (int o = 128; o > 0; o >>= 1) {
            if (t < o) red[t] += red[t + o];
            __syncthreads();
        }
        float scale = ns[0] * rsqrtf(red[0]);
        for (int i = t; i < ND; i += 256) g_vh[i] = __float2half(la[i] * scale);
        return;
    }
    size_t i = (size_t)blockIdx.x * 256 + threadIdx.x;   // 0..1048575
    const float* src;
    __half* dst;
    size_t u;
    if (i < 262144)       { src = q;  dst = g_qh;  u = i; }
    else if (i < 786432)  { src = k;  dst = g_kh;  u = i - 262144; }
    else if (i < 917504)  { src = wq; dst = g_wqh; u = i - 786432; }
    else                  { src = wk; dst = g_wkh; u = i - 917504; }
    size_t off4 = u * 2;                                  // float4 index
    float4 f0 = ((const float4*)src)[off4];
    float4 f1 = ((const float4*)src)[off4 + 1];
    __half2 h[4];
    h[0] = __floats2half2_rn(f0.x, f0.y);
    h[1] = __floats2half2_rn(f0.z, f0.w);
    h[2] = __floats2half2_rn(f1.x, f1.y);
    h[3] = __floats2half2_rn(f1.z, f1.w);
    *(uint4*)(dst + off4 * 4) = *(const uint4*)h;
}

// ---------------------------------------------------------------------------
// Fused GEMM + scores kernel. grid = 384 gemm blocks + 2048 scores blocks.
// GEMM bid = x*48 + by (u-column-major). Scores wait on g_cnt[z]==48.
// ---------------------------------------------------------------------------
__device__ __forceinline__ void gemm_path(char* smem_raw,
                                          const float* __restrict__ bias,
                                          int bid) {
    __half* As = (__half*)smem_raw;                 // [3][128][GSTRIDE]
    __half* Bs = As + 3 * 128 * GSTRIDE;

    int x = bid / 48, by = bid % 48;
    const __half* A;
    const __half* W;
    __half* C;
    const float* bptr;
    int m0;
    if (by < 16) { A = g_qh; W = g_wqh; C = g_pq; bptr = bias;    m0 = by * 128; }
    else         { A = g_kh; W = g_wkh; C = g_pk; bptr = nullptr; m0 = (by - 16) * 128; }
    int u0 = x * 128;

    int t = threadIdx.x;
    int w = t >> 5, lane = t & 31;
    int warpM = (w >> 2) * 64;
    int warpN = (w & 3) * 32;

    float acc[4][4][4];
#pragma unroll
    for (int mi = 0; mi < 4; mi++)
#pragma unroll
        for (int ni = 0; ni < 4; ni++)
#pragma unroll
            for (int i = 0; i < 4; i++) acc[mi][ni][i] = 0.f;

    int lrow = t >> 3, lch = t & 7;
    auto load_tile = [&](int buf, int k0) {
#pragma unroll
        for (int i = 0; i < 4; i++) {
            int row = lrow + i * 32;
            cp_async16(&As[(buf * 128 + row) * GSTRIDE + lch * 8],
                       A + (size_t)(m0 + row) * 1024 + k0 + lch * 8);
            cp_async16(&Bs[(buf * 128 + row) * GSTRIDE + lch * 8],
                       W + (size_t)(u0 + row) * 1024 + k0 + lch * 8);
        }
        asm volatile("cp.async.commit_group;");
    };

    load_tile(0, 0);
    load_tile(1, 64);

    int buf = 0;
    for (int it = 0; it < 16; it++) {
        if (it < 15) asm volatile("cp.async.wait_group 1;");
        else         asm volatile("cp.async.wait_group 0;");
        __syncthreads();

        if (it + 2 < 16) load_tile((buf + 2) % 3, (it + 2) * 64);

#pragma unroll
        for (int kk = 0; kk < 4; kk++) {
            unsigned a[4][4];
            int arow_l = lane & 15;
            int acol = kk * 16 + (lane >> 4) * 8;
#pragma unroll
            for (int mi = 0; mi < 4; mi++) {
                ldm_x4(a[mi][0], a[mi][1], a[mi][2], a[mi][3],
                       &As[(buf * 128 + warpM + mi * 16 + arow_l) * GSTRIDE + acol]);
            }
            unsigned b[4][2];
            int brow_l = ((lane >> 4) & 1) * 8 + (lane & 7);
            int bcol = kk * 16 + ((lane >> 3) & 1) * 8;
#pragma unroll
            for (int np = 0; np < 2; np++) {
                unsigned r0, r1, r2, r3;
                ldm_x4(r0, r1, r2, r3,
                       &Bs[(buf * 128 + warpN + np * 16 + brow_l) * GSTRIDE + bcol]);
                b[np * 2][0] = r0; b[np * 2][1] = r1;
                b[np * 2 + 1][0] = r2; b[np * 2 + 1][1] = r3;
            }
#pragma unroll
            for (int mi = 0; mi < 4; mi++)
#pragma unroll
                for (int ni = 0; ni < 4; ni++)
                    mma16816h(acc[mi][ni], a[mi], b[ni]);
        }
        buf = (buf + 1) % 3;
    }

    int g = lane >> 2, tig = lane & 3;
#pragma unroll
    for (int mi = 0; mi < 4; mi++) {
#pragma unroll
        for (int ni = 0; ni < 4; ni++) {
            int r = m0 + warpM + mi * 16 + g;
            int c = u0 + warpN + ni * 8 + tig * 2;
            float b0 = 0.f, b1 = 0.f;
            if (bptr) { b0 = __ldg(bptr + c); b1 = __ldg(bptr + c + 1); }
            *(__half2*)(C + (size_t)r * 1024 + c) =
                __floats2half2_rn(acc[mi][ni][0] + b0, acc[mi][ni][1] + b1);
            *(__half2*)(C + (size_t)(r + 8) * 1024 + c) =
                __floats2half2_rn(acc[mi][ni][2] + b0, acc[mi][ni][3] + b1);
        }
    }

    __threadfence();
    __syncthreads();
    if (threadIdx.x == 0) atomicAdd(&g_cnt[x], 1);
}

__device__ __forceinline__ void scores_path(char* smem_raw, int sid) {
    __half2* pk_s = (__half2*)smem_raw;            // [64][129]
    __half2* pq_s = pk_s + 64 * 129;               // [64][12]
    __half2* v_s  = pq_s + 64 * 12;                // [64]

    int t = threadIdx.x, w = t >> 5, lane = t & 31;
    int z   = sid >> 8;
    int r   = sid & 255;
    int bb  = r >> 3;
    int qt0 = (r & 7) * 8;
    int u0 = z * 128;
    int kidx = (w & 3) * 32 + lane;
    int qb = (w >> 2) * 4;

    if (t == 0) {
        while (((volatile int*)g_cnt)[z] < 48) __nanosleep(100);
    }
    __syncthreads();
    __threadfence();

#pragma unroll
    for (int i = 0; i < 8; i++) {
        int pos = t + i * 256;
        int u4 = pos & 15, tk = pos >> 4;
        uint4 d = *(const uint4*)(g_pk + (size_t)(tk * NB + bb) * 1024 + u0 + u4 * 8);
        const __half2* h = (const __half2*)&d;
#pragma unroll
        for (int j = 0; j < 4; j++) pk_s[(u4 * 4 + j) * 129 + tk] = h[j];
    }
    if (t < 128) {
        int u4 = t & 15, q = t >> 4;
        uint4 d = *(const uint4*)(g_pq + (size_t)((qt0 + q) * NB + bb) * 1024 + u0 + u4 * 8);
        const __half2* h = (const __half2*)&d;
#pragma unroll
        for (int j = 0; j < 4; j++) pq_s[(u4 * 4 + j) * 12 + q] = h[j];
    }
    if (t < 64) v_s[t] = ((const __half2*)g_vh)[u0 / 2 + t];
    __syncthreads();

    __half2 acc2[4];
#pragma unroll
    for (int j = 0; j < 4; j++) acc2[j] = __float2half2_rn(0.f);

#pragma unroll 4
    for (int uu = 0; uu < 64; uu++) {
        __half2 pk2 = pk_s[uu * 129 + kidx];
        __half2 v2 = v_s[uu];
        uint4 pq4 = *(const uint4*)&pq_s[uu * 12 + qb];
        const __half2* pqh = (const __half2*)&pq4;
#pragma unroll
        for (int j = 0; j < 4; j++) {
            __half2 a = __hadd2(pqh[j], pk2);
            __half2 th = (j == 3) ? ptanh2(a) : htanh2(a);
            acc2[j] = __hfma2(th, v2, acc2[j]);
        }
    }

#pragma unroll
    for (int j = 0; j < 4; j++) {
        int q = qt0 + qb + j;
        g_part_h[(((size_t)z * NB + bb) * TQ + q) * TK + kidx] =
            __float2half(__low2float(acc2[j]) + __high2float(acc2[j]));
    }
}

__global__ __launch_bounds__(256) void k_fused(const float* __restrict__ bias) {
    extern __shared__ __align__(16) char smem_raw[];
    int bid = blockIdx.x;
    if (bid < 384) gemm_path(smem_raw, bias, bid);
    else           scores_path(smem_raw, bid - 384);
}

// ---------------------------------------------------------------------------
// Kernel 3: fused softmax + tensor-core context. grid (ND/128, NB).
// Phase 1: reduce fp16 partials, softmax -> Ps smem (fp16); block x==0 also
// writes fp32 scores to d_out. Phase 2: ctx = Ps(64x128) @ keys(128x128).
// ---------------------------------------------------------------------------
__global__ __launch_bounds__(256) void k_sm_ctx_mma(float* __restrict__ ctx,
                                                    int has_scores,
                                                    float* __restrict__ scores_out) {
    __shared__ __align__(16) __half Ps[64][136];
    __shared__ __align__(16) __half Ks[64][136];

    int t = threadIdx.x, w = t >> 5, lane = t & 31;
    int bb = blockIdx.y;
    int n0 = blockIdx.x * 128;
    int warpM = (w >> 2) * 32;
    int warpN = (w & 3) * 32;

    // ---- phase 1: softmax. warp w handles q = w*8 .. w*8+7
#pragma unroll
    for (int j = 0; j < 8; j++) {
        int q = w * 8 + j;
        float x[4];
#pragma unroll
        for (int jj = 0; jj < 4; jj++) {
            int k = lane + jj * 32;
            float s = 0.f;
#pragma unroll
            for (int z = 0; z < 8; z++)
                s += __half2float(g_part_h[(((size_t)z * NB + bb) * TQ + q) * TK + k]);
            x[jj] = s;
        }
        float m = fmaxf(fmaxf(x[0], x[1]), fmaxf(x[2], x[3]));
#pragma unroll
        for (int o = 16; o > 0; o >>= 1) m = fmaxf(m, __shfl_xor_sync(0xffffffffu, m, o));
        float e0 = __expf(x[0] - m), e1 = __expf(x[1] - m);
        float e2 = __expf(x[2] - m), e3 = __expf(x[3] - m);
        float s = e0 + e1 + e2 + e3;
#pragma unroll
        for (int o = 16; o > 0; o >>= 1) s += __shfl_xor_sync(0xffffffffu, s, o);
        float inv = __fdividef(1.f, s);
        float p0 = e0 * inv, p1 = e1 * inv, p2 = e2 * inv, p3 = e3 * inv;

        Ps[q][lane]      = __float2half_rn(p0);
        Ps[q][lane + 32] = __float2half_rn(p1);
        Ps[q][lane + 64] = __float2half_rn(p2);
        Ps[q][lane + 96] = __float2half_rn(p3);

        if (has_scores && blockIdx.x == 0) {
            float* so = scores_out + ((size_t)q * NB + bb) * TK;
            so[lane] = p0; so[lane + 32] = p1; so[lane + 64] = p2; so[lane + 96] = p3;
        }
    }

    float acc[2][4][4];
#pragma unroll
    for (int mi = 0; mi < 2; mi++)
#pragma unroll
        for (int ni = 0; ni < 4; ni++)
#pragma unroll
            for (int i = 0; i < 4; i++) acc[mi][ni][i] = 0.f;

    __syncthreads();

    // ---- phase 2: MMA over two 64-k halves
#pragma unroll
    for (int kh = 0; kh < 2; kh++) {
#pragma unroll
        for (int i = 0; i < 4; i++) {
            int pos = t + i * 256;
            int r = pos >> 4, c = pos & 15;
            int tk = kh * 64 + r;
            uint4 d = *(const uint4*)(g_kh + ((size_t)tk * NB + bb) * 1024 + n0 + c * 8);
            *(uint4*)&Ks[r][c * 8] = d;
        }
        __syncthreads();

#pragma unroll
        for (int kk = 0; kk < 4; kk++) {
            unsigned a[2][4];
            int arow = lane & 15;
            int acol = kh * 64 + kk * 16 + (lane >> 4) * 8;
#pragma unroll
            for (int mi = 0; mi < 2; mi++)
                ldm_x4(a[mi][0], a[mi][1], a[mi][2], a[mi][3],
                       &Ps[warpM + mi * 16 + arow][acol]);

            unsigned b[4][2];
#pragma unroll
            for (int nf = 0; nf < 2; nf++) {
                unsigned r0, r1, r2, r3;
                ldm_x4_trans(r0, r1, r2, r3,
                             &Ks[kk * 16 + (lane & 15)][warpN + nf * 16 + (lane >> 4) * 8]);
                b[nf * 2][0] = r0;     b[nf * 2][1] = r1;
                b[nf * 2 + 1][0] = r2; b[nf * 2 + 1][1] = r3;
            }
#pragma unroll
            for (int mi = 0; mi < 2; mi++)
#pragma unroll
                for (int ni = 0; ni < 4; ni++)
                    mma16816h(acc[mi][ni], a[mi], b[ni]);
        }
        __syncthreads();
    }

    int g = lane >> 2, tig = (lane & 3) * 2;
#pragma unroll
    for (int mi = 0; mi < 2; mi++) {
#pragma unroll
        for (int ni = 0; ni < 4; ni++) {
            int q = warpM + mi * 16 + g;
            int n = n0 + warpN + ni * 8 + tig;
            float2 v0 = make_float2(acc[mi][ni][0], acc[mi][ni][1]);
            float2 v1 = make_float2(acc[mi][ni][2], acc[mi][ni][3]);
            *(float2*)(ctx + ((size_t)q * NB + bb) * 1024 + n)       = v0;
            *(float2*)(ctx + ((size_t)(q + 8) * NB + bb) * 1024 + n) = v1;
        }
    }
}

// ---------------------------------------------------------------------------
extern "C" void kernel_launch(void* const* d_in, const int* in_sizes, int n_in,
                              void* d_out, int out_size) {
    const float* query = (const float*)d_in[0];
    const float* keys  = (const float*)d_in[1];
    const float* Wq    = (const float*)d_in[2];
    const float* Wk    = (const float*)d_in[3];
    const float* la    = (const float*)d_in[4];
    const float* ns    = (const float*)d_in[5];
    const float* nbias = (const float*)d_in[6];

    float* ctx = (float*)d_out;
    const int ctx_elems = TQ * NB * ND;
    const int scr_elems = TQ * NB * TK;
    int has_scores = (out_size >= ctx_elems + scr_elems) ? 1 : 0;
    float* scores = ctx + ctx_elems;

    const int FUSED_SMEM = 3 * 128 * GSTRIDE * 2 * 2;   // 110592 B
    static int s_attr = 0;
    if (!s_attr) {
        cudaFuncSetAttribute(k_fused, cudaFuncAttributeMaxDynamicSharedMemorySize,
                             FUSED_SMEM);
        s_attr = 1;
    }

    k_convert<<<4097, 256>>>(query, keys, Wq, Wk, la, ns);

    k_fused<<<384 + 2048, 256, FUSED_SMEM>>>(nbias);

    k_sm_ctx_mma<<<dim3(ND / 128, NB), 256>>>(ctx, has_scores, scores);
}

// round 15
// speedup vs baseline: 1.0381x; 1.0381x over previous
#include <cuda_runtime.h>
#include <cuda_fp16.h>

#define TQ 64
#define TK 128
#define NB 32
#define ND 1024
#define GSTRIDE 72   // gemm smem row stride in halves

// Static scratch (no allocations allowed)
__device__ __align__(16) __half g_pq[TQ * NB * ND];
__device__ __align__(16) __half g_pk[TK * NB * ND];
__device__ __align__(16) __half g_vh[ND];
__device__ __align__(16) __half g_probs_h[NB * TQ * TK];   // [b][tq][k] fp16
__device__ __align__(16) __half g_part_h[8 * NB * TQ * TK];// [z][b][tq][k] fp16
__device__ __align__(16) __half g_qh[TQ * NB * ND];
__device__ __align__(16) __half g_kh[TK * NB * ND];
__device__ __align__(16) __half g_wqh[ND * ND];
__device__ __align__(16) __half g_wkh[ND * ND];
__device__ int g_cnt[8];   // per-u-column completion counters (48 each)

// ---------------------------------------------------------------------------
// helpers
// ---------------------------------------------------------------------------
__device__ __forceinline__ __half2 htanh2(__half2 x) {
    unsigned xi = *reinterpret_cast<unsigned*>(&x);
    unsigned ri;
    asm("tanh.approx.f16x2 %0, %1;" : "=r"(ri) : "r"(xi));
    return *reinterpret_cast<__half2*>(&ri);
}

// Pade [7/6] tanh on FMA/ALU pipes (no MUFU). Clamp to +-4.
__device__ __forceinline__ __half2 ptanh2(__half2 x) {
    x = __hmin2(__hmax2(x, __float2half2_rn(-4.0f)), __float2half2_rn(4.0f));
    __half2 t = __hmul2(x, x);
    __half2 p = __hfma2(__float2half2_rn(5.92008e-5f), t,
                        __float2half2_rn(2.237786e-2f));
    p = __hfma2(p, t, __float2half2_rn(1.0256410f));
    p = __hfma2(p, t, __float2half2_rn(8.0f));
    p = __hmul2(p, x);                                   // numerator
    __half2 qn = __hfma2(__float2half2_rn(-1.657604e-3f), t,
                         __float2half2_rn(-0.18648246f));
    qn = __hfma2(qn, t, __float2half2_rn(-3.6923077f));
    qn = __hfma2(qn, t, __float2half2_rn(-8.0f));        // -denominator
    unsigned dpos = (*reinterpret_cast<unsigned*>(&qn)) ^ 0x80008000u;
    unsigned r0b = __vsub2(0x78007800u, dpos);           // ~1/den bit trick
    __half2 r = *reinterpret_cast<__half2*>(&r0b);
    const __half2 two = __float2half2_rn(2.0f);
    r = __hmul2(r, __hfma2(qn, r, two));                 // Newton 1
    r = __hmul2(r, __hfma2(qn, r, two));                 // Newton 2
    return __hmul2(p, r);
}

__device__ __forceinline__ void ldm_x4(unsigned& r0, unsigned& r1,
                                       unsigned& r2, unsigned& r3,
                                       const void* p) {
    unsigned addr = (unsigned)__cvta_generic_to_shared(p);
    asm volatile("ldmatrix.sync.aligned.m8n8.x4.shared.b16 {%0,%1,%2,%3}, [%4];"
                 : "=r"(r0), "=r"(r1), "=r"(r2), "=r"(r3) : "r"(addr));
}

__device__ __forceinline__ void ldm_x4_trans(unsigned& r0, unsigned& r1,
                                             unsigned& r2, unsigned& r3,
                                             const void* p) {
    unsigned addr = (unsigned)__cvta_generic_to_shared(p);
    asm volatile("ldmatrix.sync.aligned.m8n8.x4.trans.shared.b16 {%0,%1,%2,%3}, [%4];"
                 : "=r"(r0), "=r"(r1), "=r"(r2), "=r"(r3) : "r"(addr));
}

__device__ __forceinline__ void mma16816h(float* c, const unsigned* a,
                                          const unsigned* b) {
    asm volatile(
        "mma.sync.aligned.m16n8k16.row.col.f32.f16.f16.f32 "
        "{%0,%1,%2,%3}, {%4,%5,%6,%7}, {%8,%9}, {%0,%1,%2,%3};"
        : "+f"(c[0]), "+f"(c[1]), "+f"(c[2]), "+f"(c[3])
        : "r"(a[0]), "r"(a[1]), "r"(a[2]), "r"(a[3]), "r"(b[0]), "r"(b[1]));
}

__device__ __forceinline__ void cp_async16(void* smem_dst, const void* gsrc) {
    unsigned d = (unsigned)__cvta_generic_to_shared(smem_dst);
    asm volatile("cp.async.cg.shared.global [%0], [%1], 16;" :: "r"(d), "l"(gsrc));
}

// ---------------------------------------------------------------------------
// Kernel A: convert fp32 -> fp16, 8 floats/thread (2xLDG.128 -> 1xSTG.128).
// Last block (4096) preps v and resets flags.
// ---------------------------------------------------------------------------
__global__ __launch_bounds__(256) void k_convert(const float* __restrict__ q,
                                                 const float* __restrict__ k,
                                                 const float* __restrict__ wq,
                                                 const float* __restrict__ wk,
                                                 const float* __restrict__ la,
                                                 const float* __restrict__ ns) {
    if (blockIdx.x == 4096) {
        __shared__ float red[256];
        int t = threadIdx.x;
        if (t < 8) g_cnt[t] = 0;
        float s = 0.f;
        for (int i = t; i < ND; i += 256) { float x = la[i]; s += x * x; }
        red[t] = s;
        __syncthreads();
        for (int o = 128; o > 0; o >>= 1) {
            if (t < o) red[t] += red[t + o];
            __syncthreads();
        }
        float scale = ns[0] * rsqrtf(red[0]);
        for (int i = t; i < ND; i += 256) g_vh[i] = __float2half(la[i] * scale);
        return;
    }
    size_t i = (size_t)blockIdx.x * 256 + threadIdx.x;   // 0..1048575
    const float* src;
    __half* dst;
    size_t u;
    if (i < 262144)       { src = q;  dst = g_qh;  u = i; }
    else if (i < 786432)  { src = k;  dst = g_kh;  u = i - 262144; }
    else if (i < 917504)  { src = wq; dst = g_wqh; u = i - 786432; }
    else                  { src = wk; dst = g_wkh; u = i - 917504; }
    size_t off4 = u * 2;                                  // float4 index
    float4 f0 = ((const float4*)src)[off4];
    float4 f1 = ((const float4*)src)[off4 + 1];
    __half2 h[4];
    h[0] = __floats2half2_rn(f0.x, f0.y);
    h[1] = __floats2half2_rn(f0.z, f0.w);
    h[2] = __floats2half2_rn(f1.x, f1.y);
    h[3] = __floats2half2_rn(f1.z, f1.w);
    *(uint4*)(dst + off4 * 4) = *(const uint4*)h;
}

// ---------------------------------------------------------------------------
// Fused GEMM + scores kernel. grid = 384 gemm blocks + 2048 scores blocks.
// GEMM bid = x*48 + by (u-column-major). Scores wait on g_cnt[z]==48.
// ---------------------------------------------------------------------------
__device__ __forceinline__ void gemm_path(char* smem_raw,
                                          const float* __restrict__ bias,
                                          int bid) {
    __half* As = (__half*)smem_raw;                 // [3][128][GSTRIDE]
    __half* Bs = As + 3 * 128 * GSTRIDE;

    int x = bid / 48, by = bid % 48;
    const __half* A;
    const __half* W;
    __half* C;
    const float* bptr;
    int m0;
    if (by < 16) { A = g_qh; W = g_wqh; C = g_pq; bptr = bias;    m0 = by * 128; }
    else         { A = g_kh; W = g_wkh; C = g_pk; bptr = nullptr; m0 = (by - 16) * 128; }
    int u0 = x * 128;

    int t = threadIdx.x;
    int w = t >> 5, lane = t & 31;
    int warpM = (w >> 2) * 64;
    int warpN = (w & 3) * 32;

    float acc[4][4][4];
#pragma unroll
    for (int mi = 0; mi < 4; mi++)
#pragma unroll
        for (int ni = 0; ni < 4; ni++)
#pragma unroll
            for (int i = 0; i < 4; i++) acc[mi][ni][i] = 0.f;

    int lrow = t >> 3, lch = t & 7;
    auto load_tile = [&](int buf, int k0) {
#pragma unroll
        for (int i = 0; i < 4; i++) {
            int row = lrow + i * 32;
            cp_async16(&As[(buf * 128 + row) * GSTRIDE + lch * 8],
                       A + (size_t)(m0 + row) * 1024 + k0 + lch * 8);
            cp_async16(&Bs[(buf * 128 + row) * GSTRIDE + lch * 8],
                       W + (size_t)(u0 + row) * 1024 + k0 + lch * 8);
        }
        asm volatile("cp.async.commit_group;");
    };

    load_tile(0, 0);
    load_tile(1, 64);

    int buf = 0;
    for (int it = 0; it < 16; it++) {
        if (it < 15) asm volatile("cp.async.wait_group 1;");
        else         asm volatile("cp.async.wait_group 0;");
        __syncthreads();

        if (it + 2 < 16) load_tile((buf + 2) % 3, (it + 2) * 64);

#pragma unroll
        for (int kk = 0; kk < 4; kk++) {
            unsigned a[4][4];
            int arow_l = lane & 15;
            int acol = kk * 16 + (lane >> 4) * 8;
#pragma unroll
            for (int mi = 0; mi < 4; mi++) {
                ldm_x4(a[mi][0], a[mi][1], a[mi][2], a[mi][3],
                       &As[(buf * 128 + warpM + mi * 16 + arow_l) * GSTRIDE + acol]);
            }
            unsigned b[4][2];
            int brow_l = ((lane >> 4) & 1) * 8 + (lane & 7);
            int bcol = kk * 16 + ((lane >> 3) & 1) * 8;
#pragma unroll
            for (int np = 0; np < 2; np++) {
                unsigned r0, r1, r2, r3;
                ldm_x4(r0, r1, r2, r3,
                       &Bs[(buf * 128 + warpN + np * 16 + brow_l) * GSTRIDE + bcol]);
                b[np * 2][0] = r0; b[np * 2][1] = r1;
                b[np * 2 + 1][0] = r2; b[np * 2 + 1][1] = r3;
            }
#pragma unroll
            for (int mi = 0; mi < 4; mi++)
#pragma unroll
                for (int ni = 0; ni < 4; ni++)
                    mma16816h(acc[mi][ni], a[mi], b[ni]);
        }
        buf = (buf + 1) % 3;
    }

    int g = lane >> 2, tig = lane & 3;
#pragma unroll
    for (int mi = 0; mi < 4; mi++) {
#pragma unroll
        for (int ni = 0; ni < 4; ni++) {
            int r = m0 + warpM + mi * 16 + g;
            int c = u0 + warpN + ni * 8 + tig * 2;
            float b0 = 0.f, b1 = 0.f;
            if (bptr) { b0 = __ldg(bptr + c); b1 = __ldg(bptr + c + 1); }
            *(__half2*)(C + (size_t)r * 1024 + c) =
                __floats2half2_rn(acc[mi][ni][0] + b0, acc[mi][ni][1] + b1);
            *(__half2*)(C + (size_t)(r + 8) * 1024 + c) =
                __floats2half2_rn(acc[mi][ni][2] + b0, acc[mi][ni][3] + b1);
        }
    }

    __threadfence();
    __syncthreads();
    if (threadIdx.x == 0) atomicAdd(&g_cnt[x], 1);
}

__device__ __forceinline__ void scores_path(char* smem_raw, int sid) {
    __half2* pk_s = (__half2*)smem_raw;            // [64][129]
    __half2* pq_s = pk_s + 64 * 129;               // [64][12]
    __half2* v_s  = pq_s + 64 * 12;                // [64]

    int t = threadIdx.x, w = t >> 5, lane = t & 31;
    int z   = sid >> 8;
    int r   = sid & 255;
    int bb  = r >> 3;
    int qt0 = (r & 7) * 8;
    int u0 = z * 128;
    int kidx = (w & 3) * 32 + lane;
    int qb = (w >> 2) * 4;

    if (t == 0) {
        while (((volatile int*)g_cnt)[z] < 48) __nanosleep(100);
    }
    __syncthreads();
    __threadfence();

#pragma unroll
    for (int i = 0; i < 8; i++) {
        int pos = t + i * 256;
        int u4 = pos & 15, tk = pos >> 4;
        uint4 d = *(const uint4*)(g_pk + (size_t)(tk * NB + bb) * 1024 + u0 + u4 * 8);
        const __half2* h = (const __half2*)&d;
#pragma unroll
        for (int j = 0; j < 4; j++) pk_s[(u4 * 4 + j) * 129 + tk] = h[j];
    }
    if (t < 128) {
        int u4 = t & 15, q = t >> 4;
        uint4 d = *(const uint4*)(g_pq + (size_t)((qt0 + q) * NB + bb) * 1024 + u0 + u4 * 8);
        const __half2* h = (const __half2*)&d;
#pragma unroll
        for (int j = 0; j < 4; j++) pq_s[(u4 * 4 + j) * 12 + q] = h[j];
    }
    if (t < 64) v_s[t] = ((const __half2*)g_vh)[u0 / 2 + t];
    __syncthreads();

    __half2 acc2[4];
#pragma unroll
    for (int j = 0; j < 4; j++) acc2[j] = __float2half2_rn(0.f);

#pragma unroll 4
    for (int uu = 0; uu < 64; uu++) {
        __half2 pk2 = pk_s[uu * 129 + kidx];
        __half2 v2 = v_s[uu];
        uint4 pq4 = *(const uint4*)&pq_s[uu * 12 + qb];
        const __half2* pqh = (const __half2*)&pq4;
#pragma unroll
        for (int j = 0; j < 4; j++) {
            __half2 a = __hadd2(pqh[j], pk2);
            __half2 th = (j == 3) ? ptanh2(a) : htanh2(a);
            acc2[j] = __hfma2(th, v2, acc2[j]);
        }
    }

#pragma unroll
    for (int j = 0; j < 4; j++) {
        int q = qt0 + qb + j;
        g_part_h[(((size_t)z * NB + bb) * TQ + q) * TK + kidx] =
            __float2half(__low2float(acc2[j]) + __high2float(acc2[j]));
    }
}

__global__ __launch_bounds__(256) void k_fused(const float* __restrict__ bias) {
    extern __shared__ __align__(16) char smem_raw[];
    int bid = blockIdx.x;
    if (bid < 384) gemm_path(smem_raw, bias, bid);
    else           scores_path(smem_raw, bid - 384);
}

// ---------------------------------------------------------------------------
// Kernel 2b: reduce fp16 partials + softmax -> fp16 probs (+fp32 scores out).
// ---------------------------------------------------------------------------
__global__ __launch_bounds__(256) void k_softmax(int has_scores,
                                                 float* __restrict__ scores_out) {
    int t = threadIdx.x, w = t >> 5, lane = t & 31;
    int bb = blockIdx.y;
    int q = blockIdx.x * 8 + w;

    float x[4];
#pragma unroll
    for (int jj = 0; jj < 4; jj++) {
        int k = lane + jj * 32;
        float s = 0.f;
#pragma unroll
        for (int z = 0; z < 8; z++)
            s += __half2float(g_part_h[(((size_t)z * NB + bb) * TQ + q) * TK + k]);
        x[jj] = s;
    }
    float m = fmaxf(fmaxf(x[0], x[1]), fmaxf(x[2], x[3]));
#pragma unroll
    for (int o = 16; o > 0; o >>= 1) m = fmaxf(m, __shfl_xor_sync(0xffffffffu, m, o));
    float e0 = __expf(x[0] - m), e1 = __expf(x[1] - m);
    float e2 = __expf(x[2] - m), e3 = __expf(x[3] - m);
    float s = e0 + e1 + e2 + e3;
#pragma unroll
    for (int o = 16; o > 0; o >>= 1) s += __shfl_xor_sync(0xffffffffu, s, o);
    float inv = __fdividef(1.f, s);
    float p0 = e0 * inv, p1 = e1 * inv, p2 = e2 * inv, p3 = e3 * inv;

    __half* pp = g_probs_h + ((size_t)bb * TQ + q) * TK;
    pp[lane]      = __float2half_rn(p0);
    pp[lane + 32] = __float2half_rn(p1);
    pp[lane + 64] = __float2half_rn(p2);
    pp[lane + 96] = __float2half_rn(p3);

    if (has_scores) {
        float* so = scores_out + ((size_t)q * NB + bb) * TK;
        so[lane] = p0; so[lane + 32] = p1; so[lane + 64] = p2; so[lane + 96] = p3;
    }
}

// ---------------------------------------------------------------------------
// Kernel 3: tensor-core context, 64-col n tiles. grid (ND/64, NB) = 512.
// Warp tile 32q x 16n; K processed in two 64-halves.
// ---------------------------------------------------------------------------
__global__ __launch_bounds__(256) void k_ctx_mma(float* __restrict__ ctx) {
    __shared__ __align__(16) __half Ps[64][136];
    __shared__ __align__(16) __half Ks[64][72];

    int t = threadIdx.x, w = t >> 5, lane = t & 31;
    int bb = blockIdx.y;
    int n0 = blockIdx.x * 64;
    int warpM = (w >> 2) * 32;   // 0 or 32
    int warpN = (w & 3) * 16;    // 0,16,32,48

    // load probs [64 q][128 k] fp16
#pragma unroll
    for (int i = 0; i < 4; i++) {
        int pos = t + i * 256;
        int q = pos >> 4, c = pos & 15;
        uint4 d = *(const uint4*)(g_probs_h + ((size_t)bb * TQ + q) * TK + c * 8);
        *(uint4*)&Ps[q][c * 8] = d;
    }

    float acc[2][2][4];
#pragma unroll
    for (int mi = 0; mi < 2; mi++)
#pragma unroll
        for (int ni = 0; ni < 2; ni++)
#pragma unroll
            for (int i = 0; i < 4; i++) acc[mi][ni][i] = 0.f;

#pragma unroll
    for (int kh = 0; kh < 2; kh++) {
        // load keys rows tk = kh*64..+63, n slice [n0, n0+64)
#pragma unroll
        for (int i = 0; i < 2; i++) {
            int pos = t + i * 256;
            int r = pos >> 3, c = pos & 7;
            int tk = kh * 64 + r;
            uint4 d = *(const uint4*)(g_kh + ((size_t)tk * NB + bb) * 1024 + n0 + c * 8);
            *(uint4*)&Ks[r][c * 8] = d;
        }
        __syncthreads();

#pragma unroll
        for (int kk = 0; kk < 4; kk++) {
            unsigned a[2][4];
            int arow = lane & 15;
            int acol = kh * 64 + kk * 16 + (lane >> 4) * 8;
#pragma unroll
            for (int mi = 0; mi < 2; mi++)
                ldm_x4(a[mi][0], a[mi][1], a[mi][2], a[mi][3],
                       &Ps[warpM + mi * 16 + arow][acol]);

            // one x4 trans: 16 k-rows x 16 n-cols -> two 8-col n fragments
            unsigned r0, r1, r2, r3;
            ldm_x4_trans(r0, r1, r2, r3,
                         &Ks[kk * 16 + (lane & 15)][warpN + (lane >> 4) * 8]);
            unsigned b[2][2];
            b[0][0] = r0; b[0][1] = r1;
            b[1][0] = r2; b[1][1] = r3;
#pragma unroll
            for (int mi = 0; mi < 2; mi++)
#pragma unroll
                for (int ni = 0; ni < 2; ni++)
                    mma16816h(acc[mi][ni], a[mi], b[ni]);
        }
        __syncthreads();
    }

    int g = lane >> 2, tig = (lane & 3) * 2;
#pragma unroll
    for (int mi = 0; mi < 2; mi++) {
#pragma unroll
        for (int ni = 0; ni < 2; ni++) {
            int q = warpM + mi * 16 + g;
            int n = n0 + warpN + ni * 8 + tig;
            float2 v0 = make_float2(acc[mi][ni][0], acc[mi][ni][1]);
            float2 v1 = make_float2(acc[mi][ni][2], acc[mi][ni][3]);
            *(float2*)(ctx + ((size_t)q * NB + bb) * 1024 + n)       = v0;
            *(float2*)(ctx + ((size_t)(q + 8) * NB + bb) * 1024 + n) = v1;
        }
    }
}

// ---------------------------------------------------------------------------
extern "C" void kernel_launch(void* const* d_in, const int* in_sizes, int n_in,
                              void* d_out, int out_size) {
    const float* query = (const float*)d_in[0];
    const float* keys  = (const float*)d_in[1];
    const float* Wq    = (const float*)d_in[2];
    const float* Wk    = (const float*)d_in[3];
    const float* la    = (const float*)d_in[4];
    const float* ns    = (const float*)d_in[5];
    const float* nbias = (const float*)d_in[6];

    float* ctx = (float*)d_out;
    const int ctx_elems = TQ * NB * ND;
    const int scr_elems = TQ * NB * TK;
    int has_scores = (out_size >= ctx_elems + scr_elems) ? 1 : 0;
    float* scores = ctx + ctx_elems;

    const int FUSED_SMEM = 3 * 128 * GSTRIDE * 2 * 2;   // 110592 B
    static int s_attr = 0;
    if (!s_attr) {
        cudaFuncSetAttribute(k_fused, cudaFuncAttributeMaxDynamicSharedMemorySize,
                             FUSED_SMEM);
        s_attr = 1;
    }

    k_convert<<<4097, 256>>>(query, keys, Wq, Wk, la, ns);

    k_fused<<<384 + 2048, 256, FUSED_SMEM>>>(nbias);

    k_softmax<<<dim3(TQ / 8, NB), 256>>>(has_scores, scores);

    k_ctx_mma<<<dim3(ND / 64, NB), 256>>>(ctx);
}